// round 1
// baseline (speedup 1.0000x reference)
#include <cuda_runtime.h>
#include <math.h>

// ---------------- scratch (device globals: allocation-free rule) ----------------
__device__ float g_h1[64u * 32u * 128u * 128u];   // 33.5M  conv1 out
__device__ float g_h2[64u * 64u * 64u * 64u];     // 16.8M  conv2 out
__device__ float g_h3[64u * 64u * 32u * 32u];     //  4.2M  conv3 out (h)
__device__ float g_z [64u * 64u * 32u * 32u];     //  4.2M  quantized
__device__ float g_d1[64u * 64u * 64u * 64u];     // 16.8M  deconv1 out
__device__ float g_d2[64u * 32u * 128u * 128u];   // 33.5M  deconv2 out
__device__ double g_loss;

// ---------------- conv k=4 s=2 p=1 + ReLU ----------------
// Each thread: one output pixel, CO_BLK output channels. Weights in shared.
template <int CIN, int COUT, int CO_BLK>
__global__ void conv_k4s2_relu(const float* __restrict__ in,
                               const float* __restrict__ w,
                               const float* __restrict__ bias,
                               float* __restrict__ out,
                               int Hin, int Win) {
    const int Hout = Hin >> 1, Wout = Win >> 1;
    __shared__ float ws[CO_BLK * CIN * 16];
    const int co0 = blockIdx.y * CO_BLK;
    const int n   = blockIdx.z;

    // weights for this co-group are contiguous: w + co0*CIN*16
    for (int i = threadIdx.x; i < CO_BLK * CIN * 16; i += blockDim.x)
        ws[i] = w[co0 * CIN * 16 + i];
    __syncthreads();

    int pix = blockIdx.x * blockDim.x + threadIdx.x;
    if (pix >= Hout * Wout) return;
    int oy = pix / Wout, ox = pix - oy * Wout;

    float acc[CO_BLK];
#pragma unroll
    for (int j = 0; j < CO_BLK; j++) acc[j] = __ldg(&bias[co0 + j]);

    const float* inb = in + (size_t)n * CIN * Hin * Win;
    for (int ci = 0; ci < CIN; ci++) {
        const float* ip = inb + (size_t)ci * Hin * Win;
#pragma unroll
        for (int ky = 0; ky < 4; ky++) {
            int iy = oy * 2 - 1 + ky;
            if ((unsigned)iy >= (unsigned)Hin) continue;
#pragma unroll
            for (int kx = 0; kx < 4; kx++) {
                int ix = ox * 2 - 1 + kx;
                if ((unsigned)ix >= (unsigned)Win) continue;
                float v = __ldg(ip + iy * Win + ix);
                int t = ky * 4 + kx;
#pragma unroll
                for (int j = 0; j < CO_BLK; j++)
                    acc[j] = fmaf(v, ws[(j * CIN + ci) * 16 + t], acc[j]);
            }
        }
    }
    size_t ob = ((size_t)n * COUT + co0) * Hout * Wout + pix;
#pragma unroll
    for (int j = 0; j < CO_BLK; j++)
        out[ob + (size_t)j * Hout * Wout] = fmaxf(acc[j], 0.f);
}

// ---------------- deconv (ConvTranspose2d) k=4 s=2 p=1 ----------------
// out[oy,ox] gathers from up to 2x2 input taps: ky = oy+1-2*iy in {0..3}.
// weight layout (Cin, Cout, 4, 4). ACT: 0=relu, 1=sigmoid.
template <int CIN, int COUT, int CO_BLK, int ACT>
__global__ void deconv_k4s2(const float* __restrict__ in,
                            const float* __restrict__ w,
                            const float* __restrict__ bias,
                            float* __restrict__ out,
                            int Hin, int Win) {
    const int Hout = Hin * 2, Wout = Win * 2;
    __shared__ float ws[CIN * CO_BLK * 16];
    const int co0 = blockIdx.y * CO_BLK;
    const int n   = blockIdx.z;

    for (int i = threadIdx.x; i < CIN * CO_BLK * 16; i += blockDim.x) {
        int ci = i / (CO_BLK * 16);
        int r  = i - ci * CO_BLK * 16;
        int j  = r >> 4;
        int t  = r & 15;
        ws[i] = w[((size_t)ci * COUT + co0 + j) * 16 + t];
    }
    __syncthreads();

    int pix = blockIdx.x * blockDim.x + threadIdx.x;
    if (pix >= Hout * Wout) return;
    int oy = pix / Wout, ox = pix - oy * Wout;

    int ky0 = (oy + 1) & 1, kx0 = (ox + 1) & 1;
    int iyA = (oy + 1 - ky0) >> 1;   // tap a=0 uses ky0, a=1 uses ky0+2 with iy-1
    int ixA = (ox + 1 - kx0) >> 1;

    float acc[CO_BLK];
#pragma unroll
    for (int j = 0; j < CO_BLK; j++) acc[j] = __ldg(&bias[co0 + j]);

    const float* inb = in + (size_t)n * CIN * Hin * Win;
    for (int ci = 0; ci < CIN; ci++) {
        const float* ip = inb + (size_t)ci * Hin * Win;
        const float* wp = &ws[ci * CO_BLK * 16];
#pragma unroll
        for (int a = 0; a < 2; a++) {
            int iy = iyA - a;
            if ((unsigned)iy >= (unsigned)Hin) continue;
            int ky = ky0 + 2 * a;
#pragma unroll
            for (int bb = 0; bb < 2; bb++) {
                int ix = ixA - bb;
                if ((unsigned)ix >= (unsigned)Win) continue;
                int kx = kx0 + 2 * bb;
                float v = __ldg(ip + iy * Win + ix);
                int t = ky * 4 + kx;
#pragma unroll
                for (int j = 0; j < CO_BLK; j++)
                    acc[j] = fmaf(v, wp[j * 16 + t], acc[j]);
            }
        }
    }
    size_t ob = ((size_t)n * COUT + co0) * Hout * Wout + pix;
#pragma unroll
    for (int j = 0; j < CO_BLK; j++) {
        float v = acc[j];
        if (ACT == 0) v = fmaxf(v, 0.f);
        else          v = 1.f / (1.f + expf(-v));
        out[ob + (size_t)j * Hout * Wout] = v;
    }
}

// ---------------- VQ: nearest codebook entry + gather + MSE loss ----------------
// 65536 points (n*1024+pix), dim 64, 512 codes. score = |c|^2 - 2 x.c (same argmin).
__global__ void vq_kernel(const float* __restrict__ h,
                          const float* __restrict__ cb,
                          float* __restrict__ z) {
    __shared__ float cs[64][65];   // padded: conflict-free norm pass
    __shared__ float cn[64];
    __shared__ float red[256];
    const int tid = threadIdx.x;
    const int pt  = blockIdx.x * 256 + tid;
    const int n   = pt >> 10;
    const int pix = pt & 1023;

    float x[64];
    const float* hb = h + (size_t)n * 64 * 1024 + pix;
#pragma unroll
    for (int c = 0; c < 64; c++) x[c] = __ldg(hb + c * 1024);

    float best = 3.4e38f;
    int   bidx = 0;
    for (int chunk = 0; chunk < 8; chunk++) {
        __syncthreads();
        for (int i = tid; i < 4096; i += 256)
            cs[i >> 6][i & 63] = cb[chunk * 4096 + i];
        __syncthreads();
        if (tid < 64) {
            float s = 0.f;
#pragma unroll
            for (int d = 0; d < 64; d++) s = fmaf(cs[tid][d], cs[tid][d], s);
            cn[tid] = s;
        }
        __syncthreads();
        for (int k = 0; k < 64; k++) {
            float dot = 0.f;
#pragma unroll
            for (int d = 0; d < 64; d++) dot = fmaf(x[d], cs[k][d], dot);
            float s = cn[k] - 2.f * dot;
            if (s < best) { best = s; bidx = chunk * 64 + k; }
        }
    }

    // gather q, write z (NCHW), accumulate squared error
    float lsum = 0.f;
    const float* qp = cb + bidx * 64;
    float* zb = z + (size_t)n * 64 * 1024 + pix;
#pragma unroll
    for (int d = 0; d < 64; d++) {
        float q = __ldg(qp + d);
        zb[d * 1024] = q;
        float df = x[d] - q;
        lsum = fmaf(df, df, lsum);
    }
    red[tid] = lsum;
    __syncthreads();
    for (int s = 128; s > 0; s >>= 1) {
        if (tid < s) red[tid] += red[tid + s];
        __syncthreads();
    }
    if (tid == 0) atomicAdd(&g_loss, (double)red[0]);
}

__global__ void zero_loss_kernel() { g_loss = 0.0; }

__global__ void write_scalars_kernel(float* __restrict__ out, long long off) {
    float v = (float)(g_loss * (1.0 / 4194304.0));  // mean over 64*64*32*32
    out[off]     = v;  // commitment
    out[off + 1] = v;  // codebook_loss (identical in forward)
}

// ---------------- launch ----------------
extern "C" void kernel_launch(void* const* d_in, const int* in_sizes, int n_in,
                              void* d_out, int out_size) {
    const float* x   = (const float*)d_in[0];
    const float* w1  = (const float*)d_in[1];
    const float* b1  = (const float*)d_in[2];
    const float* w2  = (const float*)d_in[3];
    const float* b2  = (const float*)d_in[4];
    const float* w3  = (const float*)d_in[5];
    const float* b3  = (const float*)d_in[6];
    const float* cb  = (const float*)d_in[7];
    const float* dw1 = (const float*)d_in[8];
    const float* db1 = (const float*)d_in[9];
    const float* dw2 = (const float*)d_in[10];
    const float* db2 = (const float*)d_in[11];
    const float* dw3 = (const float*)d_in[12];
    const float* db3 = (const float*)d_in[13];
    float* out = (float*)d_out;

    float *h1, *h2, *h3, *z, *d1b, *d2b;
    cudaGetSymbolAddress((void**)&h1,  g_h1);
    cudaGetSymbolAddress((void**)&h2,  g_h2);
    cudaGetSymbolAddress((void**)&h3,  g_h3);
    cudaGetSymbolAddress((void**)&z,   g_z);
    cudaGetSymbolAddress((void**)&d1b, g_d1);
    cudaGetSymbolAddress((void**)&d2b, g_d2);

    zero_loss_kernel<<<1, 1>>>();

    // encoder
    conv_k4s2_relu<3, 32, 32><<<dim3(128 * 128 / 256, 1, 64), 256>>>(x,  w1, b1, h1, 256, 256);
    conv_k4s2_relu<32, 64, 16><<<dim3(64 * 64 / 256,  4, 64), 256>>>(h1, w2, b2, h2, 128, 128);
    conv_k4s2_relu<64, 64, 8><<<dim3(32 * 32 / 256,   8, 64), 256>>>(h2, w3, b3, h3, 64, 64);

    // vector quantize (+ loss)
    vq_kernel<<<65536 / 256, 256>>>(h3, cb, z);

    // decoder
    deconv_k4s2<64, 64, 8, 0><<<dim3(64 * 64 / 256,   8, 64), 256>>>(z,   dw1, db1, d1b, 32, 32);
    deconv_k4s2<64, 32, 8, 0><<<dim3(128 * 128 / 256, 4, 64), 256>>>(d1b, dw2, db2, d2b, 64, 64);
    deconv_k4s2<32, 3, 3, 1><<<dim3(256 * 256 / 256,  1, 64), 256>>>(d2b, dw3, db3, out, 128, 128);

    // scalars at the tail of the output buffer
    write_scalars_kernel<<<1, 1>>>(out, (long long)out_size - 2);
}

// round 5
// speedup vs baseline: 1.9998x; 1.9998x over previous
#include <cuda_runtime.h>
#include <math.h>

// ---------------- scratch (device globals: allocation-free rule) ----------------
__device__ float g_h1[64u * 32u * 128u * 128u];   // conv1 out
__device__ float g_h2[64u * 64u * 64u * 64u];     // conv2 out
__device__ float g_h3[64u * 64u * 32u * 32u];     // conv3 out (h)
__device__ float g_z [64u * 64u * 32u * 32u];     // quantized
__device__ float g_d1[64u * 64u * 64u * 64u];     // deconv1 out
__device__ float g_d2[64u * 32u * 128u * 128u];   // deconv2 out
__device__ double g_loss;

// ---------------- conv k=4 s=2 p=1 + ReLU, 2D register-tiled ----------------
// Thread computes a 4(y) x 2(x) patch of outputs for CO_BLK channels.
template <int CIN, int COUT, int CO_BLK>
__global__ void conv_k4s2_relu_t(const float* __restrict__ in,
                                 const float* __restrict__ w,
                                 const float* __restrict__ bias,
                                 float* __restrict__ out,
                                 int Hin, int Win) {
    const int Hout = Hin >> 1, Wout = Win >> 1;
    const int GX = Wout >> 1;                       // x-groups (2 outputs each)
    __shared__ float ws[CO_BLK * CIN * 16];
    __shared__ float bs[CO_BLK];
    const int co0 = blockIdx.y * CO_BLK;
    const int n   = blockIdx.z;

    for (int i = threadIdx.x; i < CO_BLK * CIN * 16; i += blockDim.x)
        ws[i] = w[co0 * CIN * 16 + i];
    if (threadIdx.x < CO_BLK) bs[threadIdx.x] = bias[co0 + threadIdx.x];
    __syncthreads();

    const int g = blockIdx.x * blockDim.x + threadIdx.x;
    if (g >= GX * (Hout >> 2)) return;              // geometry guard
    const int ox0 = (g % GX) * 2;
    const int oy0 = (g / GX) * 4;

    float acc[CO_BLK][4][2];
#pragma unroll
    for (int j = 0; j < CO_BLK; j++)
#pragma unroll
        for (int s = 0; s < 4; s++) {
            acc[j][s][0] = bs[j];
            acc[j][s][1] = bs[j];
        }

    const float* inb = in + (size_t)n * CIN * Hin * Win;
    for (int ci = 0; ci < CIN; ci++) {
        const float* ip = inb + (size_t)ci * Hin * Win;
#pragma unroll
        for (int ry = 0; ry < 10; ry++) {
            const int iy = oy0 * 2 - 1 + ry;
            const bool rok = (unsigned)iy < (unsigned)Hin;
            const float* rp = ip + iy * Win;
            float c[6];
#pragma unroll
            for (int cc = 0; cc < 6; cc++) {
                int ix = ox0 * 2 - 1 + cc;
                c[cc] = (rok && (unsigned)ix < (unsigned)Win) ? __ldg(rp + ix) : 0.f;
            }
#pragma unroll
            for (int s = 0; s < 4; s++) {
                const int ky = ry - 2 * s;
                if (ky < 0 || ky > 3) continue;
#pragma unroll
                for (int kx = 0; kx < 4; kx++) {
#pragma unroll
                    for (int j = 0; j < CO_BLK; j++) {
                        float wv = ws[(j * CIN + ci) * 16 + ky * 4 + kx];
                        acc[j][s][0] = fmaf(c[kx],     wv, acc[j][s][0]);
                        acc[j][s][1] = fmaf(c[kx + 2], wv, acc[j][s][1]);
                    }
                }
            }
        }
    }
#pragma unroll
    for (int j = 0; j < CO_BLK; j++)
#pragma unroll
        for (int s = 0; s < 4; s++) {
            float2 v;
            v.x = fmaxf(acc[j][s][0], 0.f);
            v.y = fmaxf(acc[j][s][1], 0.f);
            *(float2*)&out[(((size_t)n * COUT + co0 + j) * Hout + oy0 + s) * Wout + ox0] = v;
        }
}

// ---------------- deconv (ConvTranspose2d) k=4 s=2 p=1, 2D register-tiled ----------------
// Thread computes a 4x4 output patch for CO_BLK channels. ACT: 0=relu, 1=sigmoid.
template <int CIN, int COUT, int CO_BLK, int ACT>
__global__ void deconv_k4s2_t(const float* __restrict__ in,
                              const float* __restrict__ w,
                              const float* __restrict__ bias,
                              float* __restrict__ out,
                              int Hin, int Win) {
    const int Hout = Hin * 2, Wout = Win * 2;
    const int GX = Wout >> 2;
    __shared__ float ws[CIN * CO_BLK * 16];
    __shared__ float bs[CO_BLK];
    const int co0 = blockIdx.y * CO_BLK;
    const int n   = blockIdx.z;

    for (int i = threadIdx.x; i < CIN * CO_BLK * 16; i += blockDim.x) {
        int ci = i / (CO_BLK * 16);
        int r  = i - ci * CO_BLK * 16;
        int j  = r >> 4;
        int t  = r & 15;
        ws[i] = w[((size_t)ci * COUT + co0 + j) * 16 + t];
    }
    if (threadIdx.x < CO_BLK) bs[threadIdx.x] = bias[co0 + threadIdx.x];
    __syncthreads();

    const int g = blockIdx.x * blockDim.x + threadIdx.x;
    if (g >= GX * (Hout >> 2)) return;              // geometry guard
    const int ox0 = (g % GX) * 4;
    const int oy0 = (g / GX) * 4;
    const int iyb = (oy0 >> 1) - 1;
    const int ixb = (ox0 >> 1) - 1;

    float acc[CO_BLK][4][4];
#pragma unroll
    for (int j = 0; j < CO_BLK; j++)
#pragma unroll
        for (int s = 0; s < 4; s++)
#pragma unroll
            for (int p = 0; p < 4; p++) acc[j][s][p] = bs[j];

    const float* inb = in + (size_t)n * CIN * Hin * Win;
    for (int ci = 0; ci < CIN; ci++) {
        const float* ip = inb + (size_t)ci * Hin * Win;
        float r4[4][4];
#pragma unroll
        for (int yy = 0; yy < 4; yy++) {
            const int iy = iyb + yy;
            const bool rok = (unsigned)iy < (unsigned)Hin;
#pragma unroll
            for (int xx = 0; xx < 4; xx++) {
                int ix = ixb + xx;
                r4[yy][xx] = (rok && (unsigned)ix < (unsigned)Win)
                                 ? __ldg(ip + iy * Win + ix) : 0.f;
            }
        }
#pragma unroll
        for (int j = 0; j < CO_BLK; j++) {
            float wr[16];
#pragma unroll
            for (int t = 0; t < 16; t++) wr[t] = ws[(ci * CO_BLK + j) * 16 + t];
#pragma unroll
            for (int s = 0; s < 4; s++) {
                const int ky0 = (s + 1) & 1;
                const int yyA = 1 + ((s + 1) >> 1);
#pragma unroll
                for (int p = 0; p < 4; p++) {
                    const int kx0 = (p + 1) & 1;
                    const int xxA = 1 + ((p + 1) >> 1);
#pragma unroll
                    for (int a = 0; a < 2; a++)
#pragma unroll
                        for (int b = 0; b < 2; b++)
                            acc[j][s][p] = fmaf(r4[yyA - a][xxA - b],
                                                wr[(ky0 + 2 * a) * 4 + kx0 + 2 * b],
                                                acc[j][s][p]);
                }
            }
        }
    }
#pragma unroll
    for (int j = 0; j < CO_BLK; j++)
#pragma unroll
        for (int s = 0; s < 4; s++) {
            float4 v;
            float t0 = acc[j][s][0], t1 = acc[j][s][1], t2 = acc[j][s][2], t3 = acc[j][s][3];
            if (ACT == 0) {
                v.x = fmaxf(t0, 0.f); v.y = fmaxf(t1, 0.f);
                v.z = fmaxf(t2, 0.f); v.w = fmaxf(t3, 0.f);
            } else {
                v.x = 1.f / (1.f + expf(-t0)); v.y = 1.f / (1.f + expf(-t1));
                v.z = 1.f / (1.f + expf(-t2)); v.w = 1.f / (1.f + expf(-t3));
            }
            *(float4*)&out[(((size_t)n * COUT + co0 + j) * Hout + oy0 + s) * Wout + ox0] = v;
        }
}

// ---------------- VQ: nearest codebook entry + gather + MSE loss ----------------
__global__ void vq_kernel(const float* __restrict__ h,
                          const float* __restrict__ cb,
                          float* __restrict__ z) {
    __shared__ float cs[64][65];
    __shared__ float cn[64];
    __shared__ float red[256];
    const int tid = threadIdx.x;
    const int pt  = blockIdx.x * 256 + tid;
    const int n   = pt >> 10;
    const int pix = pt & 1023;

    float x[64];
    const float* hb = h + (size_t)n * 64 * 1024 + pix;
#pragma unroll
    for (int c = 0; c < 64; c++) x[c] = __ldg(hb + c * 1024);

    float best = 3.4e38f;
    int   bidx = 0;
    for (int chunk = 0; chunk < 8; chunk++) {
        __syncthreads();
        for (int i = tid; i < 4096; i += 256)
            cs[i >> 6][i & 63] = cb[chunk * 4096 + i];
        __syncthreads();
        if (tid < 64) {
            float s = 0.f;
#pragma unroll
            for (int d = 0; d < 64; d++) s = fmaf(cs[tid][d], cs[tid][d], s);
            cn[tid] = s;
        }
        __syncthreads();
        for (int k = 0; k < 64; k++) {
            float dot = 0.f;
#pragma unroll
            for (int d = 0; d < 64; d++) dot = fmaf(x[d], cs[k][d], dot);
            float s = cn[k] - 2.f * dot;
            if (s < best) { best = s; bidx = chunk * 64 + k; }
        }
    }

    float lsum = 0.f;
    const float* qp = cb + bidx * 64;
    float* zb = z + (size_t)n * 64 * 1024 + pix;
#pragma unroll
    for (int d = 0; d < 64; d++) {
        float q = __ldg(qp + d);
        zb[d * 1024] = q;
        float df = x[d] - q;
        lsum = fmaf(df, df, lsum);
    }
    red[tid] = lsum;
    __syncthreads();
    for (int s = 128; s > 0; s >>= 1) {
        if (tid < s) red[tid] += red[tid + s];
        __syncthreads();
    }
    if (tid == 0) atomicAdd(&g_loss, (double)red[0]);
}

__global__ void zero_loss_kernel() { g_loss = 0.0; }

__global__ void write_scalars_kernel(float* __restrict__ out, long long off) {
    float v = (float)(g_loss * (1.0 / 4194304.0));
    out[off]     = v;
    out[off + 1] = v;
}

// ---------------- launch ----------------
extern "C" void kernel_launch(void* const* d_in, const int* in_sizes, int n_in,
                              void* d_out, int out_size) {
    const float* x   = (const float*)d_in[0];
    const float* w1  = (const float*)d_in[1];
    const float* b1  = (const float*)d_in[2];
    const float* w2  = (const float*)d_in[3];
    const float* b2  = (const float*)d_in[4];
    const float* w3  = (const float*)d_in[5];
    const float* b3  = (const float*)d_in[6];
    const float* cb  = (const float*)d_in[7];
    const float* dw1 = (const float*)d_in[8];
    const float* db1 = (const float*)d_in[9];
    const float* dw2 = (const float*)d_in[10];
    const float* db2 = (const float*)d_in[11];
    const float* dw3 = (const float*)d_in[12];
    const float* db3 = (const float*)d_in[13];
    float* out = (float*)d_out;

    float *h1, *h2, *h3, *z, *d1b, *d2b;
    cudaGetSymbolAddress((void**)&h1,  g_h1);
    cudaGetSymbolAddress((void**)&h2,  g_h2);
    cudaGetSymbolAddress((void**)&h3,  g_h3);
    cudaGetSymbolAddress((void**)&z,   g_z);
    cudaGetSymbolAddress((void**)&d1b, g_d1);
    cudaGetSymbolAddress((void**)&d2b, g_d2);

    zero_loss_kernel<<<1, 1>>>();

    // encoder: thread tiles 4y x 2x; groups = (Hout/4)*(Wout/2), blockDim 128
    conv_k4s2_relu_t<3, 32, 8><<<dim3(16, 4, 64), 128>>>(x,  w1, b1, h1, 256, 256); // 2048 grp
    conv_k4s2_relu_t<32, 64, 8><<<dim3(4, 8, 64), 128>>>(h1, w2, b2, h2, 128, 128); // 512 grp (FIXED)
    conv_k4s2_relu_t<64, 64, 8><<<dim3(1, 8, 64), 128>>>(h2, w3, b3, h3, 64, 64);   // 128 grp

    // vector quantize (+ loss)
    vq_kernel<<<65536 / 256, 256>>>(h3, cb, z);

    // decoder: thread tiles 4y x 4x; groups = (Hout/4)*(Wout/4)
    deconv_k4s2_t<64, 64, 4, 0><<<dim3(2, 16, 64), 128>>>(z,   dw1, db1, d1b, 32, 32);   // 256 grp
    deconv_k4s2_t<64, 32, 4, 0><<<dim3(8, 8, 64), 128>>>(d1b, dw2, db2, d2b, 64, 64);    // 1024 grp
    deconv_k4s2_t<32, 3, 3, 1><<<dim3(32, 1, 64), 128>>>(d2b, dw3, db3, out, 128, 128);  // 4096 grp

    write_scalars_kernel<<<1, 1>>>(out, (long long)out_size - 2);
}